// round 10
// baseline (speedup 1.0000x reference)
#include <cuda_runtime.h>

#define T_DIM 1024
#define F_DIM 256
#define F4    (F_DIM / 4)
#define UNITS 32
#define AW    64
#define HALF  32
#define B_DIM 4
#define NROWS (B_DIM * T_DIM)
#define AP    72            // padded weight stride: zeros [0..2], data [3..66], zeros [67..71]

typedef unsigned long long u64;

__device__ float g_q[NROWS * UNITS];
__device__ float g_k[NROWS * UNITS];
__device__ float g_af[NROWS * AP];             // scalar weights, zero-padded

__device__ __forceinline__ float tanh_approx(float x) {
    float y;
    asm("tanh.approx.f32 %0, %1;" : "=f"(y) : "f"(x));
    return y;
}
__device__ __forceinline__ u64 ffma2(u64 a, u64 b, u64 c) {
    u64 d;
    asm("fma.rn.f32x2 %0, %1, %2, %3;" : "=l"(d) : "l"(a), "l"(b), "l"(c));
    return d;
}
__device__ __forceinline__ u64 pack2(float a, float b) {
    u64 d;
    asm("mov.b64 %0, {%1, %2};" : "=l"(d) : "f"(a), "f"(b));
    return d;
}
__device__ __forceinline__ u64 dup2(float w) {
    u64 d;
    asm("mov.b64 %0, {%1, %1};" : "=l"(d) : "f"(w));
    return d;
}
__device__ __forceinline__ float hadd2(u64 v) {
    unsigned lo, hi;
    asm("mov.b64 {%0, %1}, %2;" : "=r"(lo), "=r"(hi) : "l"(v));
    return __uint_as_float(lo) + __uint_as_float(hi);
}
__device__ __forceinline__ void f4_to_u64(float4 v, u64& a, u64& b) {
    asm("mov.b64 %0, {%2, %3};\n\tmov.b64 %1, {%4, %5};"
        : "=l"(a), "=l"(b) : "f"(v.x), "f"(v.y), "f"(v.z), "f"(v.w));
}
__device__ __forceinline__ void u64_to_f4(u64 a, u64 b, float4& v) {
    asm("mov.b64 {%0, %1}, %4;\n\tmov.b64 {%2, %3}, %5;"
        : "=f"(v.x), "=f"(v.y), "=f"(v.z), "=f"(v.w) : "l"(a), "l"(b));
}

// ---------------------------------------------------------------------------
// Kernel 1 (R7 version, measured 9.3us): q = x@Wt + bh, k = x@Wx.
// W packed in registers, hoisted over 2 rows per warp. 512 blocks x 8 warps.
// ---------------------------------------------------------------------------
__global__ void __launch_bounds__(256) qk_kernel(
    const float* __restrict__ x,
    const float* __restrict__ Wt,
    const float* __restrict__ Wx,
    const float* __restrict__ bh)
{
    __shared__ float4 xs4[8 * F4];                       // 8 rows = 8KB

    const int tid = threadIdx.x;
    const int r0  = blockIdx.x * 8;

    const float4* xg = reinterpret_cast<const float4*>(x) + (size_t)r0 * F4;
    xs4[tid]       = xg[tid];
    xs4[tid + 256] = xg[tid + 256];
    __syncthreads();

    const int  wid  = tid >> 5;
    const int  lane = tid & 31;
    const bool is_q = (wid < 4);
    const int  rp   = wid & 3;                           // row pair 0..3

    const float* __restrict__ W = is_q ? Wt : Wx;        // [F][U]
    const float4* __restrict__ x0 = xs4 + (2 * rp + 0) * F4;
    const float4* __restrict__ x1 = xs4 + (2 * rp + 1) * F4;

    u64 acc0a = 0ull, acc0b = 0ull, acc1a = 0ull, acc1b = 0ull;

    #pragma unroll 2
    for (int c = 0; c < 16; c++) {                       // 16 f per chunk
        u64 w[8];
        #pragma unroll
        for (int ff = 0; ff < 8; ff++) {
            const float wa = W[(c * 16 + 2 * ff + 0) * UNITS + lane];
            const float wb = W[(c * 16 + 2 * ff + 1) * UNITS + lane];
            w[ff] = pack2(wa, wb);
        }
        #pragma unroll
        for (int k = 0; k < 4; k++) {
            u64 va, vb;
            f4_to_u64(x0[c * 4 + k], va, vb);            // LDS.128 broadcast
            acc0a = ffma2(va, w[2 * k + 0], acc0a);
            acc0b = ffma2(vb, w[2 * k + 1], acc0b);
            f4_to_u64(x1[c * 4 + k], va, vb);
            acc1a = ffma2(va, w[2 * k + 0], acc1a);
            acc1b = ffma2(vb, w[2 * k + 1], acc1b);
        }
    }

    const float bias = is_q ? bh[lane] : 0.f;
    float* __restrict__ G = is_q ? g_q : g_k;
    G[(size_t)(r0 + 2 * rp + 0) * UNITS + lane] = hadd2(acc0a) + hadd2(acc0b) + bias;
    G[(size_t)(r0 + 2 * rp + 1) * UNITS + lane] = hadd2(acc1a) + hadd2(acc1b) + bias;
}

// ---------------------------------------------------------------------------
// Kernel 2 (R9 version): band logits + softmax -> g_af (scalar, zero-padded).
// grid (T/8, B) = 512 blocks, 256 threads.
// ---------------------------------------------------------------------------
__global__ void __launch_bounds__(256) weights_kernel(
    const float* __restrict__ Wa, const float* __restrict__ ba)
{
    const int b  = blockIdx.y;
    const int t0 = blockIdx.x * 8;
    const int sbase = t0 - HALF;
    const int SR = 8 + AW - 1;                       // 71 staged k rows

    __shared__ float ks[71 * 33];
    __shared__ float qs[8 * UNITS];
    __shared__ float was[UNITS];
    __shared__ float es[8 * AW];

    const int tid = threadIdx.x;

    for (int idx = tid; idx < SR * UNITS; idx += 256) {
        const int srel = idx >> 5, u = idx & 31;
        int s = sbase + srel;
        s = min(max(s, 0), T_DIM - 1);               // OOB rows masked via es
        ks[srel * 33 + u] = g_k[(size_t)(b * T_DIM + s) * UNITS + u];
    }
    if (tid < 8 * UNITS)
        qs[tid] = g_q[(size_t)(b * T_DIM + t0) * UNITS + tid];
    if (tid < UNITS) was[tid] = Wa[tid];
    __syncthreads();

    #pragma unroll
    for (int l = 0; l < 2; l++) {
        const int idx = tid + l * 256;               // 512 logits
        const int tl  = idx >> 6;
        const int j   = idx & 63;
        const int s   = t0 + tl - HALF + j;
        float e = -1e30f;
        if (s >= 0 && s < T_DIM) {
            const int srel = tl + j;
            float acc = 0.f;
            #pragma unroll
            for (int u = 0; u < UNITS; u++)
                acc += was[u] * tanh_approx(qs[tl * UNITS + u] + ks[srel * 33 + u]);
            e = acc + ba[0];
        }
        es[tl * AW + j] = e;
    }
    __syncthreads();

    const int wid = tid >> 5, lane = tid & 31;
    {
        const float e0 = es[wid * AW + lane];
        const float e1 = es[wid * AW + lane + 32];
        float m = fmaxf(e0, e1);
        #pragma unroll
        for (int o = 16; o; o >>= 1)
            m = fmaxf(m, __shfl_xor_sync(0xffffffffu, m, o));
        const float p0 = __expf(e0 - m);
        const float p1 = __expf(e1 - m);
        float sum = p0 + p1;
        #pragma unroll
        for (int o = 16; o; o >>= 1)
            sum += __shfl_xor_sync(0xffffffffu, sum, o);
        const float inv = 1.f / sum;
        const float a0 = p0 * inv, a1 = p1 * inv;    // exactly 0 when masked
        const size_t row = (size_t)(b * T_DIM + t0 + wid) * AP;
        g_af[row + 3 + lane]  = a0;
        g_af[row + 35 + lane] = a1;
        if (lane < 3) g_af[row + lane]      = 0.f;   // left pad
        if (lane < 5) g_af[row + 67 + lane] = 0.f;   // right pad
    }
}

// ---------------------------------------------------------------------------
// Kernel 3 (R9 version): v = banded a @ x. grid (T/8, B), 128 threads.
// Warp = (4 consecutive t, f-half): x-reuse x4, predicate-free inner loop.
// ---------------------------------------------------------------------------
__global__ void __launch_bounds__(128) out_kernel(
    const float* __restrict__ x, float* __restrict__ out)
{
    const int b  = blockIdx.y;
    const int t0 = blockIdx.x * 8;

    __shared__ float asf[8 * AP];                    // 2.3KB weights
    const int tid = threadIdx.x;
    for (int idx = tid; idx < 8 * AP; idx += 128)
        asf[idx] = g_af[(size_t)(b * T_DIM + t0) * AP + idx];
    __syncthreads();

    const int wid  = tid >> 5;
    const int lane = tid & 31;
    const int qd   = wid & 1;                        // t-quad
    const int h    = wid >> 1;                       // f-half
    const int f4   = h * 32 + lane;
    const int tq   = t0 + 4 * qd;

    const float4* __restrict__ xg4 =
        reinterpret_cast<const float4*>(x) + (size_t)b * T_DIM * F4;
    const float* aw0 = asf + (4 * qd + 0) * AP + 3;
    const float* aw1 = asf + (4 * qd + 1) * AP + 2;
    const float* aw2 = asf + (4 * qd + 2) * AP + 1;
    const float* aw3 = asf + (4 * qd + 3) * AP + 0;

    u64 a0 = 0ull, b0 = 0ull, a1 = 0ull, b1 = 0ull;
    u64 a2 = 0ull, b2 = 0ull, a3 = 0ull, b3 = 0ull;

    if (t0 >= HALF && t0 + 38 < T_DIM) {
        const float4* xp = xg4 + (size_t)(tq - HALF) * F4 + f4;
        #pragma unroll 4
        for (int i = 0; i < AW + 3; i++) {           // 67-row union window
            u64 xa, xb;
            f4_to_u64(*xp, xa, xb);                  // LDG.128
            xp += F4;
            const u64 w0 = dup2(aw0[i]);             // LDS.32 + mov
            const u64 w1 = dup2(aw1[i]);
            const u64 w2 = dup2(aw2[i]);
            const u64 w3 = dup2(aw3[i]);
            a0 = ffma2(xa, w0, a0);  b0 = ffma2(xb, w0, b0);
            a1 = ffma2(xa, w1, a1);  b1 = ffma2(xb, w1, b1);
            a2 = ffma2(xa, w2, a2);  b2 = ffma2(xb, w2, b2);
            a3 = ffma2(xa, w3, a3);  b3 = ffma2(xb, w3, b3);
        }
    } else {
        #pragma unroll 4
        for (int i = 0; i < AW + 3; i++) {
            int s = tq - HALF + i;
            s = min(max(s, 0), T_DIM - 1);           // weight is 0 when OOB
            u64 xa, xb;
            f4_to_u64(xg4[(size_t)s * F4 + f4], xa, xb);
            const u64 w0 = dup2(aw0[i]);
            const u64 w1 = dup2(aw1[i]);
            const u64 w2 = dup2(aw2[i]);
            const u64 w3 = dup2(aw3[i]);
            a0 = ffma2(xa, w0, a0);  b0 = ffma2(xb, w0, b0);
            a1 = ffma2(xa, w1, a1);  b1 = ffma2(xb, w1, b1);
            a2 = ffma2(xa, w2, a2);  b2 = ffma2(xb, w2, b2);
            a3 = ffma2(xa, w3, a3);  b3 = ffma2(xb, w3, b3);
        }
    }

    float4* __restrict__ og =
        reinterpret_cast<float4*>(out) + (size_t)b * T_DIM * F4;
    float4 o;
    u64_to_f4(a0, b0, o); og[(size_t)(tq + 0) * F4 + f4] = o;
    u64_to_f4(a1, b1, o); og[(size_t)(tq + 1) * F4 + f4] = o;
    u64_to_f4(a2, b2, o); og[(size_t)(tq + 2) * F4 + f4] = o;
    u64_to_f4(a3, b3, o); og[(size_t)(tq + 3) * F4 + f4] = o;
}

extern "C" void kernel_launch(void* const* d_in, const int* in_sizes, int n_in,
                              void* d_out, int out_size)
{
    const float* x  = (const float*)d_in[0];
    const float* Wt = (const float*)d_in[1];
    const float* Wx = (const float*)d_in[2];
    const float* bh = (const float*)d_in[3];
    const float* Wa = (const float*)d_in[4];
    const float* ba = (const float*)d_in[5];
    float* out = (float*)d_out;

    qk_kernel<<<NROWS / 8, 256>>>(x, Wt, Wx, bh);
    weights_kernel<<<dim3(T_DIM / 8, B_DIM), 256>>>(Wa, ba);
    out_kernel<<<dim3(T_DIM / 8, B_DIM), 128>>>(x, out);
}

// round 11
// speedup vs baseline: 1.0144x; 1.0144x over previous
#include <cuda_runtime.h>

#define T_DIM 1024
#define F_DIM 256
#define F4    (F_DIM / 4)
#define UNITS 32
#define AW    64
#define HALF  32
#define B_DIM 4
#define NROWS (B_DIM * T_DIM)
#define AP    72            // padded weight stride: zeros [0..2], data [3..66], zeros [67..71]

typedef unsigned long long u64;

__device__ float g_q[NROWS * UNITS];
__device__ float g_k[NROWS * UNITS];

__device__ __forceinline__ float tanh_approx(float x) {
    float y;
    asm("tanh.approx.f32 %0, %1;" : "=f"(y) : "f"(x));
    return y;
}
__device__ __forceinline__ u64 ffma2(u64 a, u64 b, u64 c) {
    u64 d;
    asm("fma.rn.f32x2 %0, %1, %2, %3;" : "=l"(d) : "l"(a), "l"(b), "l"(c));
    return d;
}
__device__ __forceinline__ u64 addx2(u64 a, u64 b) {
    u64 d;
    asm("add.rn.f32x2 %0, %1, %2;" : "=l"(d) : "l"(a), "l"(b));
    return d;
}
__device__ __forceinline__ u64 dup2(float w) {
    u64 d;
    asm("mov.b64 %0, {%1, %1};" : "=l"(d) : "f"(w));
    return d;
}
__device__ __forceinline__ void f4_to_u64(float4 v, u64& a, u64& b) {
    asm("mov.b64 %0, {%2, %3};\n\tmov.b64 %1, {%4, %5};"
        : "=l"(a), "=l"(b) : "f"(v.x), "f"(v.y), "f"(v.z), "f"(v.w));
}
__device__ __forceinline__ void u64_to_f4(u64 a, u64 b, float4& v) {
    asm("mov.b64 {%0, %1}, %4;\n\tmov.b64 {%2, %3}, %5;"
        : "=f"(v.x), "=f"(v.y), "=f"(v.z), "=f"(v.w) : "l"(a), "l"(b));
}
__device__ __forceinline__ u64 shfl_xor_u64(u64 v, int m) {
    double d = __longlong_as_double((long long)v);
    d = __shfl_xor_sync(0xffffffffu, d, m);
    return (u64)__double_as_longlong(d);
}

// ---------------------------------------------------------------------------
// Kernel 1: q = x@Wt + bh, k = x@Wx. Transposed-W scheme, 4 rows/warp.
// 256 blocks x 8 warps = 2048 warps. Lane owns (u-quad, f-subgroup).
// Per c-iter (4 f): 1 LDG.128 (W) + 4 LDS.32 bcast + 4 dup + 8 FFMA2
// covering 4 rows x 4 f x 8 units = 512 lane-MACs.
// ---------------------------------------------------------------------------
__global__ void __launch_bounds__(256) qk_kernel(
    const float* __restrict__ x,
    const float* __restrict__ Wt,
    const float* __restrict__ Wx,
    const float* __restrict__ bh)
{
    __shared__ float xs[16 * F_DIM];                 // 16 rows = 16KB

    const int tid = threadIdx.x;
    const int r0  = blockIdx.x * 16;

    const float4* xg  = reinterpret_cast<const float4*>(x) + (size_t)r0 * F4;
    float4*       xs4 = reinterpret_cast<float4*>(xs);
    #pragma unroll
    for (int i = 0; i < 4; i++)
        xs4[tid + i * 256] = xg[tid + i * 256];
    __syncthreads();

    const int  wid  = tid >> 5;
    const int  lane = tid & 31;
    const bool is_q = (wid < 4);
    const int  rq   = wid & 3;                       // row quad 0..3
    const int  fg   = lane >> 3;                     // f-subgroup 0..3
    const int  u4   = lane & 7;                      // unit quad 0..7

    const float4* __restrict__ Wf4 =
        reinterpret_cast<const float4*>(is_q ? Wt : Wx);   // [F][8 quads]
    const float* xr0 = xs + (4 * rq + 0) * F_DIM;
    const float* xr1 = xs + (4 * rq + 1) * F_DIM;
    const float* xr2 = xs + (4 * rq + 2) * F_DIM;
    const float* xr3 = xs + (4 * rq + 3) * F_DIM;

    u64 a0 = 0ull, b0 = 0ull, a1 = 0ull, b1 = 0ull;
    u64 a2 = 0ull, b2 = 0ull, a3 = 0ull, b3 = 0ull;

    #pragma unroll 8
    for (int c = 0; c < 64; c++) {                   // lane's f = 4c + fg
        const float4 wv = Wf4[32 * c + lane];        // LDG.128, coalesced
        u64 w01, w23;
        f4_to_u64(wv, w01, w23);
        const u64 x0 = dup2(xr0[4 * c + fg]);        // LDS.32
        const u64 x1 = dup2(xr1[4 * c + fg]);
        const u64 x2 = dup2(xr2[4 * c + fg]);
        const u64 x3 = dup2(xr3[4 * c + fg]);
        a0 = ffma2(x0, w01, a0);  b0 = ffma2(x0, w23, b0);
        a1 = ffma2(x1, w01, a1);  b1 = ffma2(x1, w23, b1);
        a2 = ffma2(x2, w01, a2);  b2 = ffma2(x2, w23, b2);
        a3 = ffma2(x3, w01, a3);  b3 = ffma2(x3, w23, b3);
    }

    // combine f-subgroups (lanes 8 apart share u4)
    a0 = addx2(a0, shfl_xor_u64(a0, 8));  a0 = addx2(a0, shfl_xor_u64(a0, 16));
    b0 = addx2(b0, shfl_xor_u64(b0, 8));  b0 = addx2(b0, shfl_xor_u64(b0, 16));
    a1 = addx2(a1, shfl_xor_u64(a1, 8));  a1 = addx2(a1, shfl_xor_u64(a1, 16));
    b1 = addx2(b1, shfl_xor_u64(b1, 8));  b1 = addx2(b1, shfl_xor_u64(b1, 16));
    a2 = addx2(a2, shfl_xor_u64(a2, 8));  a2 = addx2(a2, shfl_xor_u64(a2, 16));
    b2 = addx2(b2, shfl_xor_u64(b2, 8));  b2 = addx2(b2, shfl_xor_u64(b2, 16));
    a3 = addx2(a3, shfl_xor_u64(a3, 8));  a3 = addx2(a3, shfl_xor_u64(a3, 16));
    b3 = addx2(b3, shfl_xor_u64(b3, 8));  b3 = addx2(b3, shfl_xor_u64(b3, 16));

    // lane group fg writes row (4*rq + fg): units 4*u4 .. 4*u4+3 as float4
    const u64 wa = (fg == 0) ? a0 : (fg == 1) ? a1 : (fg == 2) ? a2 : a3;
    const u64 wb = (fg == 0) ? b0 : (fg == 1) ? b1 : (fg == 2) ? b2 : b3;
    float4 o;
    u64_to_f4(wa, wb, o);
    if (is_q) {
        const float4 bv = reinterpret_cast<const float4*>(bh)[u4];
        o.x += bv.x; o.y += bv.y; o.z += bv.z; o.w += bv.w;
    }
    float4* __restrict__ G4 = reinterpret_cast<float4*>(is_q ? g_q : g_k);
    G4[(size_t)(r0 + 4 * rq + fg) * 8 + u4] = o;     // STG.128
}

// ---------------------------------------------------------------------------
// Kernel 2 (fused): logits + softmax + v = a @ x for an 8-t tile.
// grid (T/8, B) = 512 blocks, 128 threads (4 warps).
// Phase D: warp = (4 consecutive t, f-half), scalar smem weights,
// zero-padded -> predicate-free inner loop.
// ---------------------------------------------------------------------------
__global__ void __launch_bounds__(128) attn_kernel(
    const float* __restrict__ x,
    const float* __restrict__ Wa,
    const float* __restrict__ ba,
    float* __restrict__ out)
{
    const int b  = blockIdx.y;
    const int t0 = blockIdx.x * 8;
    const int sbase = t0 - HALF;
    const int SR = 8 + AW - 1;                       // 71 staged k rows

    __shared__ float ks[71 * 33];
    __shared__ float qs[8 * UNITS];
    __shared__ float was[UNITS];
    __shared__ float es[8 * AW];
    __shared__ float asf[8 * AP];                    // zero-padded weights

    const int tid = threadIdx.x;

    for (int idx = tid; idx < SR * UNITS; idx += 128) {
        const int srel = idx >> 5, u = idx & 31;
        int s = sbase + srel;
        s = min(max(s, 0), T_DIM - 1);               // OOB rows masked via es
        ks[srel * 33 + u] = g_k[(size_t)(b * T_DIM + s) * UNITS + u];
    }
    for (int idx = tid; idx < 8 * UNITS; idx += 128)
        qs[idx] = g_q[(size_t)(b * T_DIM + t0) * UNITS + idx];
    if (tid < UNITS) was[tid] = Wa[tid];
    __syncthreads();

    // --- logits: 4 per thread (8 t x 64 j = 512) ---------------------------
    #pragma unroll
    for (int l = 0; l < 4; l++) {
        const int idx = tid + l * 128;
        const int tl  = idx >> 6;
        const int j   = idx & 63;
        const int s   = t0 + tl - HALF + j;
        float e = -1e30f;
        if (s >= 0 && s < T_DIM) {
            const int srel = tl + j;
            float acc = 0.f;
            #pragma unroll
            for (int u = 0; u < UNITS; u++)
                acc += was[u] * tanh_approx(qs[tl * UNITS + u] + ks[srel * 33 + u]);
            e = acc + ba[0];
        }
        es[tl * AW + j] = e;
    }
    __syncthreads();

    // --- softmax: 4 warps x 2 t rows each; write zero-padded scalars -------
    const int wid = tid >> 5, lane = tid & 31;
    #pragma unroll
    for (int k = 0; k < 2; k++) {
        const int tl = wid * 2 + k;
        const float e0 = es[tl * AW + lane];
        const float e1 = es[tl * AW + lane + 32];
        float m = fmaxf(e0, e1);
        #pragma unroll
        for (int o = 16; o; o >>= 1)
            m = fmaxf(m, __shfl_xor_sync(0xffffffffu, m, o));
        const float p0 = __expf(e0 - m);
        const float p1 = __expf(e1 - m);
        float sum = p0 + p1;
        #pragma unroll
        for (int o = 16; o; o >>= 1)
            sum += __shfl_xor_sync(0xffffffffu, sum, o);
        const float inv = 1.f / sum;
        asf[tl * AP + 3 + lane]  = p0 * inv;         // exactly 0 when masked
        asf[tl * AP + 35 + lane] = p1 * inv;
        if (lane < 3) asf[tl * AP + lane]      = 0.f;   // left pad
        if (lane < 5) asf[tl * AP + 67 + lane] = 0.f;   // right pad
    }
    __syncthreads();

    // --- phase D: warp = (4 consecutive t, f-half) -------------------------
    const int qd = wid & 1;                          // t-quad
    const int h  = wid >> 1;                         // f-half
    const int f4 = h * 32 + lane;
    const int tq = t0 + 4 * qd;

    const float4* __restrict__ xg4 =
        reinterpret_cast<const float4*>(x) + (size_t)b * T_DIM * F4;
    // row r weight for window index i is asf[(4qd+r)*AP + 3 + i - r]
    const float* aw0 = asf + (4 * qd + 0) * AP + 3;
    const float* aw1 = asf + (4 * qd + 1) * AP + 2;
    const float* aw2 = asf + (4 * qd + 2) * AP + 1;
    const float* aw3 = asf + (4 * qd + 3) * AP + 0;

    u64 a0 = 0ull, b0 = 0ull, a1 = 0ull, b1 = 0ull;
    u64 a2 = 0ull, b2 = 0ull, a3 = 0ull, b3 = 0ull;

    if (t0 >= HALF && t0 + 38 < T_DIM) {
        const float4* xp = xg4 + (size_t)(tq - HALF) * F4 + f4;
        #pragma unroll 4
        for (int i = 0; i < AW + 3; i++) {           // 67-row union window
            u64 xa, xb;
            f4_to_u64(*xp, xa, xb);                  // LDG.128
            xp += F4;
            const u64 w0 = dup2(aw0[i]);             // LDS.32 + mov
            const u64 w1 = dup2(aw1[i]);
            const u64 w2 = dup2(aw2[i]);
            const u64 w3 = dup2(aw3[i]);
            a0 = ffma2(xa, w0, a0);  b0 = ffma2(xb, w0, b0);
            a1 = ffma2(xa, w1, a1);  b1 = ffma2(xb, w1, b1);
            a2 = ffma2(xa, w2, a2);  b2 = ffma2(xb, w2, b2);
            a3 = ffma2(xa, w3, a3);  b3 = ffma2(xb, w3, b3);
        }
    } else {
        #pragma unroll 4
        for (int i = 0; i < AW + 3; i++) {
            int s = tq - HALF + i;
            s = min(max(s, 0), T_DIM - 1);           // weight is 0 when OOB
            u64 xa, xb;
            f4_to_u64(xg4[(size_t)s * F4 + f4], xa, xb);
            const u64 w0 = dup2(aw0[i]);
            const u64 w1 = dup2(aw1[i]);
            const u64 w2 = dup2(aw2[i]);
            const u64 w3 = dup2(aw3[i]);
            a0 = ffma2(xa, w0, a0);  b0 = ffma2(xb, w0, b0);
            a1 = ffma2(xa, w1, a1);  b1 = ffma2(xb, w1, b1);
            a2 = ffma2(xa, w2, a2);  b2 = ffma2(xb, w2, b2);
            a3 = ffma2(xa, w3, a3);  b3 = ffma2(xb, w3, b3);
        }
    }

    float4* __restrict__ og =
        reinterpret_cast<float4*>(out) + (size_t)b * T_DIM * F4;
    float4 o;
    u64_to_f4(a0, b0, o); og[(size_t)(tq + 0) * F4 + f4] = o;
    u64_to_f4(a1, b1, o); og[(size_t)(tq + 1) * F4 + f4] = o;
    u64_to_f4(a2, b2, o); og[(size_t)(tq + 2) * F4 + f4] = o;
    u64_to_f4(a3, b3, o); og[(size_t)(tq + 3) * F4 + f4] = o;
}

extern "C" void kernel_launch(void* const* d_in, const int* in_sizes, int n_in,
                              void* d_out, int out_size)
{
    const float* x  = (const float*)d_in[0];
    const float* Wt = (const float*)d_in[1];
    const float* Wx = (const float*)d_in[2];
    const float* bh = (const float*)d_in[3];
    const float* Wa = (const float*)d_in[4];
    const float* ba = (const float*)d_in[5];
    float* out = (float*)d_out;

    qk_kernel<<<NROWS / 16, 256>>>(x, Wt, Wx, bh);
    attn_kernel<<<dim3(T_DIM / 8, B_DIM), 128>>>(x, Wa, ba, out);
}

// round 12
// speedup vs baseline: 1.1604x; 1.1439x over previous
#include <cuda_runtime.h>

#define T_DIM 1024
#define F_DIM 256
#define F4    (F_DIM / 4)
#define UNITS 32
#define AW    64
#define HALF  32
#define B_DIM 4
#define NROWS (B_DIM * T_DIM)
#define AP    66            // padded weight stride (zeros at [0] and [65])

typedef unsigned long long u64;

__device__ float g_q[NROWS * UNITS];
__device__ float g_k[NROWS * UNITS];

__device__ __forceinline__ float tanh_approx(float x) {
    float y;
    asm("tanh.approx.f32 %0, %1;" : "=f"(y) : "f"(x));
    return y;
}
__device__ __forceinline__ u64 ffma2(u64 a, u64 b, u64 c) {
    u64 d;
    asm("fma.rn.f32x2 %0, %1, %2, %3;" : "=l"(d) : "l"(a), "l"(b), "l"(c));
    return d;
}
__device__ __forceinline__ u64 addx2(u64 a, u64 b) {
    u64 d;
    asm("add.rn.f32x2 %0, %1, %2;" : "=l"(d) : "l"(a), "l"(b));
    return d;
}
__device__ __forceinline__ u64 pack2(float a, float b) {
    u64 d;
    asm("mov.b64 %0, {%1, %2};" : "=l"(d) : "f"(a), "f"(b));
    return d;
}
__device__ __forceinline__ u64 dup2(float w) {
    u64 d;
    asm("mov.b64 %0, {%1, %1};" : "=l"(d) : "f"(w));
    return d;
}
__device__ __forceinline__ void f4_to_u64(float4 v, u64& a, u64& b) {
    asm("mov.b64 %0, {%2, %3};\n\tmov.b64 %1, {%4, %5};"
        : "=l"(a), "=l"(b) : "f"(v.x), "f"(v.y), "f"(v.z), "f"(v.w));
}
__device__ __forceinline__ void u64_to_f4(u64 a, u64 b, float4& v) {
    asm("mov.b64 {%0, %1}, %4;\n\tmov.b64 {%2, %3}, %5;"
        : "=f"(v.x), "=f"(v.y), "=f"(v.z), "=f"(v.w) : "l"(a), "l"(b));
}
__device__ __forceinline__ u64 shfl_xor_u64(u64 v, int m) {
    double d = __longlong_as_double((long long)v);
    d = __shfl_xor_sync(0xffffffffu, d, m);
    return (u64)__double_as_longlong(d);
}

// ---------------------------------------------------------------------------
// Kernel 1 (R9 version): q = x@Wt + bh, k = x@Wx. Transposed-W scheme,
// 2 rows/warp, 512 blocks x 8 warps. Lane owns (u-quad, f-subgroup).
// ---------------------------------------------------------------------------
__global__ void __launch_bounds__(256) qk_kernel(
    const float* __restrict__ x,
    const float* __restrict__ Wt,
    const float* __restrict__ Wx,
    const float* __restrict__ bh)
{
    __shared__ float xs[8 * F_DIM];                  // 8 rows = 8KB

    const int tid = threadIdx.x;
    const int r0  = blockIdx.x * 8;

    const float4* xg  = reinterpret_cast<const float4*>(x) + (size_t)r0 * F4;
    float4*       xs4 = reinterpret_cast<float4*>(xs);
    xs4[tid]       = xg[tid];
    xs4[tid + 256] = xg[tid + 256];
    __syncthreads();

    const int  wid  = tid >> 5;
    const int  lane = tid & 31;
    const bool is_q = (wid < 4);
    const int  rp   = wid & 3;                       // row pair
    const int  fg   = lane >> 3;                     // f-subgroup 0..3
    const int  u4   = lane & 7;                      // unit quad 0..7

    const float4* __restrict__ Wf4 =
        reinterpret_cast<const float4*>(is_q ? Wt : Wx);   // [F][8 quads]
    const float* xr0 = xs + (2 * rp + 0) * F_DIM;
    const float* xr1 = xs + (2 * rp + 1) * F_DIM;

    u64 a0 = 0ull, b0 = 0ull, a1 = 0ull, b1 = 0ull;

    #pragma unroll 8
    for (int c = 0; c < 64; c++) {                   // lane's f = 4c + fg
        const float4 wv = Wf4[32 * c + lane];        // LDG.128, coalesced
        u64 w01, w23;
        f4_to_u64(wv, w01, w23);
        const u64 xv0 = dup2(xr0[4 * c + fg]);       // LDS.32 broadcast
        const u64 xv1 = dup2(xr1[4 * c + fg]);
        a0 = ffma2(xv0, w01, a0);  b0 = ffma2(xv0, w23, b0);
        a1 = ffma2(xv1, w01, a1);  b1 = ffma2(xv1, w23, b1);
    }

    // combine f-subgroups: lanes 8 apart share u4
    a0 = addx2(a0, shfl_xor_u64(a0, 8));  a0 = addx2(a0, shfl_xor_u64(a0, 16));
    b0 = addx2(b0, shfl_xor_u64(b0, 8));  b0 = addx2(b0, shfl_xor_u64(b0, 16));
    a1 = addx2(a1, shfl_xor_u64(a1, 8));  a1 = addx2(a1, shfl_xor_u64(a1, 16));
    b1 = addx2(b1, shfl_xor_u64(b1, 8));  b1 = addx2(b1, shfl_xor_u64(b1, 16));

    if (fg < 2) {                                    // fg 0 -> row0, fg 1 -> row1
        const u64 wa = fg ? a1 : a0;
        const u64 wb = fg ? b1 : b0;
        float4 o;
        u64_to_f4(wa, wb, o);
        if (is_q) {
            const float4 bv = reinterpret_cast<const float4*>(bh)[u4];
            o.x += bv.x; o.y += bv.y; o.z += bv.z; o.w += bv.w;
        }
        float4* __restrict__ G4 =
            reinterpret_cast<float4*>(is_q ? g_q : g_k);
        G4[(size_t)(r0 + 2 * rp + fg) * 8 + u4] = o; // STG.128
    }
}

// ---------------------------------------------------------------------------
// Kernel 2 (R7 version): fused logits + softmax + v = a @ x for an 8-t tile.
// grid (T/8, B) = 512 blocks, 256 threads (8 warps).
// Weights stored as zero-padded dup-pairs -> predicate-free phase D.
// ---------------------------------------------------------------------------
__global__ void __launch_bounds__(256) attn_out_kernel(
    const float* __restrict__ x,
    const float* __restrict__ Wa,
    const float* __restrict__ ba,
    float* __restrict__ out)
{
    const int b  = blockIdx.y;
    const int t0 = blockIdx.x * 8;
    const int sbase = t0 - HALF;
    const int SR = 8 + AW - 1;                   // 71 staged k rows

    __shared__ float ks[71 * 33];                // padded, conflict-free
    __shared__ float qs[8 * UNITS];
    __shared__ float was[UNITS];
    __shared__ float es[8 * AW];
    __shared__ u64   as2[8 * AP];                // dup pairs, zeros at [0],[65]

    const int tid = threadIdx.x;

    for (int idx = tid; idx < SR * UNITS; idx += 256) {
        const int srel = idx >> 5, u = idx & 31;
        int s = sbase + srel;
        s = min(max(s, 0), T_DIM - 1);           // OOB rows masked via es
        ks[srel * 33 + u] = g_k[(size_t)(b * T_DIM + s) * UNITS + u];
    }
    if (tid < 8 * UNITS)
        qs[tid] = g_q[(size_t)(b * T_DIM + t0) * UNITS + tid];
    if (tid < UNITS) was[tid] = Wa[tid];
    __syncthreads();

    // --- logits: 2 per thread (8 t x 64 j = 512) ---------------------------
    #pragma unroll
    for (int l = 0; l < 2; l++) {
        const int idx = tid + l * 256;
        const int tl  = idx >> 6;
        const int j   = idx & 63;
        const int s   = t0 + tl - HALF + j;
        float e = -1e30f;
        if (s >= 0 && s < T_DIM) {
            const int srel = tl + j;
            float acc = 0.f;
            #pragma unroll
            for (int u = 0; u < UNITS; u++)
                acc += was[u] * tanh_approx(qs[tl * UNITS + u] + ks[srel * 33 + u]);
            e = acc + ba[0];
        }
        es[tl * AW + j] = e;
    }
    __syncthreads();

    // --- softmax: 8 warps, one t each; write zero-padded dup pairs ---------
    const int wid = tid >> 5, lane = tid & 31;
    {
        const float e0 = es[wid * AW + lane];
        const float e1 = es[wid * AW + lane + 32];
        float m = fmaxf(e0, e1);
        #pragma unroll
        for (int o = 16; o; o >>= 1)
            m = fmaxf(m, __shfl_xor_sync(0xffffffffu, m, o));
        const float p0 = __expf(e0 - m);
        const float p1 = __expf(e1 - m);
        float sum = p0 + p1;
        #pragma unroll
        for (int o = 16; o; o >>= 1)
            sum += __shfl_xor_sync(0xffffffffu, sum, o);
        const float inv = 1.f / sum;
        const float a0 = p0 * inv, a1 = p1 * inv;   // exactly 0 when masked
        as2[wid * AP + 1 + lane]      = pack2(a0, a0);
        as2[wid * AP + 33 + lane]     = pack2(a1, a1);
        if (lane == 0) {
            as2[wid * AP + 0]      = 0ull;          // pad left
            as2[wid * AP + AW + 1] = 0ull;          // pad right
        }
    }
    __syncthreads();

    // --- phase D: warp = (2 t, f-half). Union window 65 rows. --------------
    const int p  = wid & 3;                      // t pair: 2p, 2p+1
    const int h  = wid >> 2;
    const int f4 = h * 32 + lane;
    const int ta = t0 + 2 * p;

    const float4* __restrict__ xg4 =
        reinterpret_cast<const float4*>(x) + (size_t)b * T_DIM * F4;
    const u64* awa = as2 + (2 * p + 0) * AP;     // index [1+i]
    const u64* awb = as2 + (2 * p + 1) * AP;     // index [i]

    u64 acc0a = 0ull, acc0b = 0ull, acc1a = 0ull, acc1b = 0ull;

    if (t0 >= HALF && t0 + 7 + HALF < T_DIM) {
        // ---- interior fast path: no clamps, pointer walk ----
        const float4* xp = xg4 + (size_t)(ta - HALF) * F4 + f4;
        #pragma unroll 5
        for (int i = 0; i < AW + 1; i++) {
            u64 xa, xb;
            f4_to_u64(*xp, xa, xb);              // LDG.128
            xp += F4;
            const u64 w0 = awa[i + 1];           // LDS.64 dup pair
            const u64 w1 = awb[i];
            acc0a = ffma2(xa, w0, acc0a);
            acc0b = ffma2(xb, w0, acc0b);
            acc1a = ffma2(xa, w1, acc1a);
            acc1b = ffma2(xb, w1, acc1b);
        }
    } else {
        // ---- boundary path: clamp s; OOB weights are exactly 0 ----
        #pragma unroll 5
        for (int i = 0; i < AW + 1; i++) {
            int s = ta - HALF + i;
            s = min(max(s, 0), T_DIM - 1);
            u64 xa, xb;
            f4_to_u64(xg4[(size_t)s * F4 + f4], xa, xb);
            const u64 w0 = awa[i + 1];
            const u64 w1 = awb[i];
            acc0a = ffma2(xa, w0, acc0a);
            acc0b = ffma2(xb, w0, acc0b);
            acc1a = ffma2(xa, w1, acc1a);
            acc1b = ffma2(xb, w1, acc1b);
        }
    }

    float4 o0, o1;
    u64_to_f4(acc0a, acc0b, o0);
    u64_to_f4(acc1a, acc1b, o1);
    float4* __restrict__ og =
        reinterpret_cast<float4*>(out) + (size_t)b * T_DIM * F4;
    og[(size_t)(ta + 0) * F4 + f4] = o0;
    og[(size_t)(ta + 1) * F4 + f4] = o1;
}

extern "C" void kernel_launch(void* const* d_in, const int* in_sizes, int n_in,
                              void* d_out, int out_size)
{
    const float* x  = (const float*)d_in[0];
    const float* Wt = (const float*)d_in[1];
    const float* Wx = (const float*)d_in[2];
    const float* bh = (const float*)d_in[3];
    const float* Wa = (const float*)d_in[4];
    const float* ba = (const float*)d_in[5];
    float* out = (float*)d_out;

    qk_kernel<<<NROWS / 8, 256>>>(x, Wt, Wx, bh);
    attn_out_kernel<<<dim3(T_DIM / 8, B_DIM), 256>>>(x, Wa, ba, out);
}